// round 11
// baseline (speedup 1.0000x reference)
#include <cuda_runtime.h>
#include <cstdint>

#define B_  4
#define C_  64
#define H_  96
#define W_  96
#define O_  128
#define HW_ (H_*W_)
#define K2_ 9
#define NJ_ 27
#define CK_ (C_*K2_)   // 576
#define CG_ 4
#define CPG (C_/CG_)   // 16

// scratch
__device__ float g_part[(size_t)CG_*B_*NJ_*HW_];
__device__ float g_V[(size_t)B_*CK_*HW_];
__device__ float g_Wd[(size_t)CK_*2*O_];   // duplicated weights [k][2o(+dup)]

// ---------------------------------------------------------------------------
// Kernel A: offset+modulator 3x3 conv (unchanged from R10)
// ---------------------------------------------------------------------------
__global__ void __launch_bounds__(256) conv_offmod_partial(
    const float* __restrict__ x, const float* __restrict__ ow,
    const float* __restrict__ mw)
{
    __shared__ float ws[CPG*14*9];
    __shared__ float xs[34*36];

    const int tx = threadIdx.x;
    const int ty = threadIdx.y;
    const int tid = ty*8 + tx;
    const int zz = blockIdx.z;
    const int half = zz & 1;
    const int g = (zz >> 1) & 3;
    const int b = zz >> 3;
    const int JB = half * 14;
    const int jn = half ? 13 : 14;
    const int c0 = g * CPG;
    const int x0t = blockIdx.x*32 - 1;
    const int y0t = blockIdx.y*32 - 1;

    const int jn9 = jn * 9;
    for (int idx = tid; idx < CPG*jn9; idx += 256) {
        int c = idx / jn9, r = idx % jn9;
        int j = r / 9 + JB, t = r % 9;
        float v = (j < 18) ? ow[(j*64 + c0 + c)*9 + t]
                           : mw[((j-18)*64 + c0 + c)*9 + t];
        ws[idx] = v;
    }

    float acc[14][4];
#pragma unroll
    for (int j = 0; j < 14; j++)
#pragma unroll
        for (int i = 0; i < 4; i++) acc[j][i] = 0.f;

    const float* xb = x + (b*C_ + c0)*HW_;

    for (int c = 0; c < CPG; c++) {
        __syncthreads();
        for (int idx = tid; idx < 34*34; idx += 256) {
            int r = idx / 34, cc = idx % 34;
            int gy = y0t + r, gx = x0t + cc;
            float v = 0.f;
            if (gy >= 0 && gy < H_ && gx >= 0 && gx < W_)
                v = xb[c*HW_ + gy*W_ + gx];
            xs[r*36 + cc] = v;
        }
        __syncthreads();

        float xv[3][6];
#pragma unroll
        for (int dy = 0; dy < 3; dy++)
#pragma unroll
            for (int dx = 0; dx < 6; dx++)
                xv[dy][dx] = xs[(ty + dy)*36 + tx*4 + dx];

        const float* wc = ws + c*jn9;
#pragma unroll
        for (int j = 0; j < 14; j++) {
            if (j < jn) {
#pragma unroll
                for (int t = 0; t < 9; t++) {
                    float wv = wc[j*9 + t];
#pragma unroll
                    for (int i = 0; i < 4; i++)
                        acc[j][i] = fmaf(wv, xv[t/3][t%3 + i], acc[j][i]);
                }
            }
        }
    }

    const int h  = y0t + 1 + ty;
    const int w0 = x0t + 1 + tx*4;
    float* outb = g_part + ((size_t)(g*B_ + b)*NJ_ + JB)*HW_ + h*W_ + w0;
#pragma unroll
    for (int j = 0; j < 14; j++) {
        if (j < jn) {
            float4 v = make_float4(acc[j][0], acc[j][1], acc[j][2], acc[j][3]);
            *(float4*)(outb + (size_t)j*HW_) = v;
        }
    }
}

// ---------------------------------------------------------------------------
// Kernel T: build duplicated-transposed weights [k][2o] = [k][2o+1] = W[o][k]
// ---------------------------------------------------------------------------
__global__ void dup_w(const float* __restrict__ dw)
{
    int i = blockIdx.x*256 + threadIdx.x;
    if (i < O_*CK_) {
        int o = i / CK_, k = i % CK_;
        float v = dw[i];
        g_Wd[(size_t)k*(2*O_) + 2*o]     = v;
        g_Wd[(size_t)k*(2*O_) + 2*o + 1] = v;
    }
}

// ---------------------------------------------------------------------------
// Kernel G: combine partials (+bias/sigmoid), bilinear gather -> g_V
// (unchanged from R10)
// ---------------------------------------------------------------------------
#define PT 64

__global__ void gather_kernel(
    const float* __restrict__ x, const float* __restrict__ ob,
    const float* __restrict__ mb)
{
    __shared__ float wgt[4*K2_*PT];
    __shared__ int   gof[4*K2_*PT];

    const int tid = threadIdx.x;
    const int b   = blockIdx.y;
    const int pg0 = blockIdx.x * PT;

    const float* xb = x + b*C_*HW_;

    for (int t = tid; t < K2_*PT; t += 256) {
        int k2 = t / PT, p = t % PT;
        int pg = pg0 + p;
        int h  = pg / W_, w = pg % W_;

        float dy = ob[2*k2], dx = ob[2*k2+1], mv = mb[k2];
#pragma unroll
        for (int g = 0; g < CG_; g++) {
            const float* pb = g_part + (((size_t)g*B_ + b)*NJ_)*HW_ + pg;
            dy += pb[(size_t)(2*k2)*HW_];
            dx += pb[(size_t)(2*k2+1)*HW_];
            mv += pb[(size_t)(18+k2)*HW_];
        }
        float m = 2.f / (1.f + __expf(-mv));

        float py = (float)(h - 1 + k2/3) + dy;
        float px = (float)(w - 1 + k2%3) + dx;
        float fy = floorf(py), fx = floorf(px);
        float ly = py - fy,    lx = px - fx;
        int y0 = (int)fy, x0i = (int)fx;
        float vy0 = (y0   >= 0 && y0   < H_) ? 1.f : 0.f;
        float vy1 = (y0+1 >= 0 && y0+1 < H_) ? 1.f : 0.f;
        float vx0 = (x0i   >= 0 && x0i   < W_) ? 1.f : 0.f;
        float vx1 = (x0i+1 >= 0 && x0i+1 < W_) ? 1.f : 0.f;
        int cy0 = min(max(y0, 0), H_-1),   cy1 = min(max(y0+1, 0), H_-1);
        int cx0 = min(max(x0i, 0), W_-1),  cx1 = min(max(x0i+1, 0), W_-1);
        int base = k2*PT + p;
        wgt[0*(K2_*PT) + base] = (1.f-ly)*(1.f-lx)*vy0*vx0*m;
        wgt[1*(K2_*PT) + base] = (1.f-ly)*lx      *vy0*vx1*m;
        wgt[2*(K2_*PT) + base] = ly*(1.f-lx)      *vy1*vx0*m;
        wgt[3*(K2_*PT) + base] = ly*lx            *vy1*vx1*m;
        gof[0*(K2_*PT) + base] = cy0*W_ + cx0;
        gof[1*(K2_*PT) + base] = cy0*W_ + cx1;
        gof[2*(K2_*PT) + base] = cy1*W_ + cx0;
        gof[3*(K2_*PT) + base] = cy1*W_ + cx1;
    }
    __syncthreads();

    const int p  = tid & 63;
    const int kr = tid >> 6;   // 0..3
    float* Vb = g_V + (size_t)b*CK_*HW_ + pg0 + p;

#pragma unroll
    for (int k2 = 0; k2 < K2_; k2++) {
        int base = k2*PT + p;
        float w0 = wgt[0*(K2_*PT) + base];
        float w1 = wgt[1*(K2_*PT) + base];
        float w2 = wgt[2*(K2_*PT) + base];
        float w3 = wgt[3*(K2_*PT) + base];
        const float* p0 = xb + kr*HW_ + gof[0*(K2_*PT) + base];
        const float* p1 = xb + kr*HW_ + gof[1*(K2_*PT) + base];
        const float* p2 = xb + kr*HW_ + gof[2*(K2_*PT) + base];
        const float* p3 = xb + kr*HW_ + gof[3*(K2_*PT) + base];
        float* op = Vb + (size_t)(kr*K2_ + k2)*HW_;

#pragma unroll 4
        for (int c = kr; c < C_; c += 4) {
            float v = w0*__ldg(p0) + w1*__ldg(p1)
                    + w2*__ldg(p2) + w3*__ldg(p3);
            *op = v;
            p0 += 4*HW_; p1 += 4*HW_; p2 += 4*HW_; p3 += 4*HW_;
            op += (size_t)4*K2_*HW_;
        }
    }
}

// ---------------------------------------------------------------------------
// Kernel M: GEMM out[b][o][p] = sum_k W[o][k] * V[b][k][p]
// 128o x 128p tile, 256 threads, 8o x 8p thread tile, FFMA2.
// W stored duplicated in smem -> A operands (w,w) read directly (no packs).
// cp.async double buffering (KCM=32), XOR chunk swizzles on both tiles.
// ---------------------------------------------------------------------------
#define KCM 32
#define WD_FLOATS (KCM*2*O_)    // 8192 per buffer
#define VS_FLOATS (KCM*128)     // 4096 per buffer
#define VOFF (2*WD_FLOATS)      // 16384

#define WPERM(cx) ((cx) ^ (((cx) >> 3) & 7))   // 64 chunks per W row
#define CSWZ(cx)  ((cx) ^ (((cx) >> 3) & 1))   // 32 chunks per V row

__device__ __forceinline__ void cp16(float* s, const float* g) {
    unsigned sa = (unsigned)__cvta_generic_to_shared(s);
    asm volatile("cp.async.cg.shared.global [%0], [%1], 16;"
                 :: "r"(sa), "l"(g));
}

__global__ void __launch_bounds__(256) gemm_kernel(float* __restrict__ out)
{
    extern __shared__ float sm[];   // Wd[2][32][256] | Vs[2][32][128]

    const int tid = threadIdx.x;
    const int b   = blockIdx.y;
    const int px0 = blockIdx.x * 128;

    const int to = tid & 15;
    const int tp = tid >> 4;
    // W: thread's 4 swizzled chunk offsets (floats) in a 256-float dup row
    const int wq0 = WPERM(4*to + 0) * 4;
    const int wq1 = WPERM(4*to + 1) * 4;
    const int wq2 = WPERM(4*to + 2) * 4;
    const int wq3 = WPERM(4*to + 3) * 4;
    // V: two swizzled chunk offsets in a 128-float row
    const int vo0 = CSWZ(tp*2)     * 4;
    const int vo1 = CSWZ(tp*2 + 1) * 4;

    const float* Vb = g_V + (size_t)b*CK_*HW_ + px0;

    unsigned long long acc2[8][4];   // [o][p-pair]
#pragma unroll
    for (int i = 0; i < 8; i++)
#pragma unroll
        for (int j = 0; j < 4; j++) acc2[i][j] = 0ull;

    auto issue = [&](int buf, int kc) {
        float* wbuf = sm + buf*WD_FLOATS;
        float* vbuf = sm + VOFF + buf*VS_FLOATS;
        const float* wg = g_Wd + (size_t)kc*(2*O_);
        // W: 32 rows x 64 chunks = 2048 chunks, 8 per thread
#pragma unroll
        for (int i = 0; i < 8; i++) {
            int idx = tid + i*256;
            int r = idx >> 6, q = idx & 63;
            cp16(wbuf + r*(2*O_) + WPERM(q)*4, wg + (size_t)r*(2*O_) + q*4);
        }
        // V: 32 rows x 32 chunks = 1024 chunks, 4 per thread
#pragma unroll
        for (int i = 0; i < 4; i++) {
            int idx = tid + i*256;
            int r = idx >> 5, q = idx & 31;
            cp16(vbuf + r*128 + CSWZ(q)*4, Vb + (size_t)(kc + r)*HW_ + q*4);
        }
        asm volatile("cp.async.commit_group;");
    };

    issue(0, 0);
    int buf = 0;

    const int NCH = CK_/KCM;   // 18
    for (int c = 0; c < NCH; c++) {
        if (c + 1 < NCH) {
            issue(buf ^ 1, (c+1)*KCM);
            asm volatile("cp.async.wait_group 1;");
        } else {
            asm volatile("cp.async.wait_group 0;");
        }
        __syncthreads();

        const float* wbuf = sm + buf*WD_FLOATS;
        const float* vbuf = sm + VOFF + buf*VS_FLOATS;

#pragma unroll 4
        for (int kk = 0; kk < KCM; kk++) {
            const float* wr = wbuf + kk*(2*O_);
            float4 a0 = *(const float4*)(wr + wq0);   // (w0,w0,w1,w1)
            float4 a1 = *(const float4*)(wr + wq1);   // (w2,w2,w3,w3)
            float4 a2 = *(const float4*)(wr + wq2);
            float4 a3 = *(const float4*)(wr + wq3);
            const float* vr = vbuf + kk*128;
            float4 v0 = *(const float4*)(vr + vo0);
            float4 v1 = *(const float4*)(vr + vo1);
            unsigned long long au[8];
            au[0] = ((const unsigned long long*)&a0)[0];
            au[1] = ((const unsigned long long*)&a0)[1];
            au[2] = ((const unsigned long long*)&a1)[0];
            au[3] = ((const unsigned long long*)&a1)[1];
            au[4] = ((const unsigned long long*)&a2)[0];
            au[5] = ((const unsigned long long*)&a2)[1];
            au[6] = ((const unsigned long long*)&a3)[0];
            au[7] = ((const unsigned long long*)&a3)[1];
            unsigned long long bv0 = ((const unsigned long long*)&v0)[0];
            unsigned long long bv1 = ((const unsigned long long*)&v0)[1];
            unsigned long long bv2 = ((const unsigned long long*)&v1)[0];
            unsigned long long bv3 = ((const unsigned long long*)&v1)[1];
#pragma unroll
            for (int i = 0; i < 8; i++) {
                asm("fma.rn.f32x2 %0, %1, %2, %0;" : "+l"(acc2[i][0]) : "l"(au[i]), "l"(bv0));
                asm("fma.rn.f32x2 %0, %1, %2, %0;" : "+l"(acc2[i][1]) : "l"(au[i]), "l"(bv1));
                asm("fma.rn.f32x2 %0, %1, %2, %0;" : "+l"(acc2[i][2]) : "l"(au[i]), "l"(bv2));
                asm("fma.rn.f32x2 %0, %1, %2, %0;" : "+l"(acc2[i][3]) : "l"(au[i]), "l"(bv3));
            }
        }
        __syncthreads();
        buf ^= 1;
    }

    // epilogue
    const int o0 = to * 8;
    const int p0 = tp * 8;
#pragma unroll
    for (int i = 0; i < 8; i++) {
        float* dst = out + (size_t)(b*O_ + o0 + i)*HW_ + px0 + p0;
        *(float4*)(dst)     = *(float4*)(&acc2[i][0]);
        *(float4*)(dst + 4) = *(float4*)(&acc2[i][2]);
    }
}

// ---------------------------------------------------------------------------
extern "C" void kernel_launch(void* const* d_in, const int* in_sizes, int n_in,
                              void* d_out, int out_size)
{
    const float* x  = (const float*)d_in[0];
    const float* ow = (const float*)d_in[1];
    const float* ob = (const float*)d_in[2];
    const float* mw = (const float*)d_in[3];
    const float* mb = (const float*)d_in[4];
    const float* dw = (const float*)d_in[5];
    float* out = (float*)d_out;

    const int smemM = (2*WD_FLOATS + 2*VS_FLOATS) * 4;   // 96KB
    cudaFuncSetAttribute(gemm_kernel,
                         cudaFuncAttributeMaxDynamicSharedMemorySize, smemM);

    dim3 gA(3, 3, B_*CG_*2), bA(8, 32);   // 288 blocks, one launch
    conv_offmod_partial<<<gA, bA>>>(x, ow, mw);

    dup_w<<<(O_*CK_ + 255)/256, 256>>>(dw);

    dim3 gG(HW_/PT, B_);
    gather_kernel<<<gG, 256>>>(x, ob, mb);

    dim3 gM(HW_/128, B_);   // 72 x 4 = 288 blocks
    gemm_kernel<<<gM, 256, smemM>>>(out);
}

// round 12
// speedup vs baseline: 1.1169x; 1.1169x over previous
#include <cuda_runtime.h>
#include <cstdint>

#define B_  4
#define C_  64
#define H_  96
#define W_  96
#define O_  128
#define HW_ (H_*W_)
#define K2_ 9
#define NJ_ 27
#define CK_ (C_*K2_)   // 576
#define CG_ 4
#define CPG (C_/CG_)   // 16

// scratch
__device__ float g_part[(size_t)CG_*B_*NJ_*HW_];
__device__ float g_Wt[(size_t)CK_*O_];   // transposed deform weights [k][o]

// ---------------------------------------------------------------------------
// Kernel A: offset+modulator 3x3 conv (unchanged)
// ---------------------------------------------------------------------------
__global__ void __launch_bounds__(256) conv_offmod_partial(
    const float* __restrict__ x, const float* __restrict__ ow,
    const float* __restrict__ mw)
{
    __shared__ float ws[CPG*14*9];
    __shared__ float xs[34*36];

    const int tx = threadIdx.x;
    const int ty = threadIdx.y;
    const int tid = ty*8 + tx;
    const int zz = blockIdx.z;
    const int half = zz & 1;
    const int g = (zz >> 1) & 3;
    const int b = zz >> 3;
    const int JB = half * 14;
    const int jn = half ? 13 : 14;
    const int c0 = g * CPG;
    const int x0t = blockIdx.x*32 - 1;
    const int y0t = blockIdx.y*32 - 1;

    const int jn9 = jn * 9;
    for (int idx = tid; idx < CPG*jn9; idx += 256) {
        int c = idx / jn9, r = idx % jn9;
        int j = r / 9 + JB, t = r % 9;
        float v = (j < 18) ? ow[(j*64 + c0 + c)*9 + t]
                           : mw[((j-18)*64 + c0 + c)*9 + t];
        ws[idx] = v;
    }

    float acc[14][4];
#pragma unroll
    for (int j = 0; j < 14; j++)
#pragma unroll
        for (int i = 0; i < 4; i++) acc[j][i] = 0.f;

    const float* xb = x + (b*C_ + c0)*HW_;

    for (int c = 0; c < CPG; c++) {
        __syncthreads();
        for (int idx = tid; idx < 34*34; idx += 256) {
            int r = idx / 34, cc = idx % 34;
            int gy = y0t + r, gx = x0t + cc;
            float v = 0.f;
            if (gy >= 0 && gy < H_ && gx >= 0 && gx < W_)
                v = xb[c*HW_ + gy*W_ + gx];
            xs[r*36 + cc] = v;
        }
        __syncthreads();

        float xv[3][6];
#pragma unroll
        for (int dy = 0; dy < 3; dy++)
#pragma unroll
            for (int dx = 0; dx < 6; dx++)
                xv[dy][dx] = xs[(ty + dy)*36 + tx*4 + dx];

        const float* wc = ws + c*jn9;
#pragma unroll
        for (int j = 0; j < 14; j++) {
            if (j < jn) {
#pragma unroll
                for (int t = 0; t < 9; t++) {
                    float wv = wc[j*9 + t];
#pragma unroll
                    for (int i = 0; i < 4; i++)
                        acc[j][i] = fmaf(wv, xv[t/3][t%3 + i], acc[j][i]);
                }
            }
        }
    }

    const int h  = y0t + 1 + ty;
    const int w0 = x0t + 1 + tx*4;
    float* outb = g_part + ((size_t)(g*B_ + b)*NJ_ + JB)*HW_ + h*W_ + w0;
#pragma unroll
    for (int j = 0; j < 14; j++) {
        if (j < jn) {
            float4 v = make_float4(acc[j][0], acc[j][1], acc[j][2], acc[j][3]);
            *(float4*)(outb + (size_t)j*HW_) = v;
        }
    }
}

// ---------------------------------------------------------------------------
// Kernel T: transpose deform weights [O][CK] -> [CK][O]
// ---------------------------------------------------------------------------
__global__ void transpose_w(const float* __restrict__ dw)
{
    int i = blockIdx.x*256 + threadIdx.x;
    if (i < O_*CK_) {
        int o = i / CK_, k = i % CK_;
        g_Wt[(size_t)k*O_ + o] = dw[i];
    }
}

// ---------------------------------------------------------------------------
// Kernel F: FUSED gather + GEMM.
// Per block: 128 pixels x 128 outputs, K=576 in 18 chunks of 32.
// Stage 0: bilinear params for 9x128 samples -> smem (36KB).
// Chunk loop: gather chunk c+1 into Vs[nxt] (LDG+FMA+STS, LSU pipe) while
// computing chunk c with FFMA2 (fma pipe). W via cp.async double buffer.
// smem = 100KB -> 2 blocks/SM. Thread tile 8o x 8p.
// ---------------------------------------------------------------------------
#define KCM 32
#define NPAR (K2_*128)          // 1152 params
#define WSF (KCM*128)           // 4096 floats per W buffer
#define VSF (KCM*128)           // 4096 floats per V buffer
#define CSWZ(cx) ((cx) ^ (((cx) >> 3) & 1))

__device__ __forceinline__ void cp16(float* s, const float* g) {
    unsigned sa = (unsigned)__cvta_generic_to_shared(s);
    asm volatile("cp.async.cg.shared.global [%0], [%1], 16;"
                 :: "r"(sa), "l"(g));
}
__device__ __forceinline__ unsigned long long pack2(float v) {
    unsigned long long r;
    unsigned int u = __float_as_uint(v);
    asm("mov.b64 %0, {%1, %1};" : "=l"(r) : "r"(u));
    return r;
}

__global__ void __launch_bounds__(256, 2) fused_kernel(
    const float* __restrict__ x, const float* __restrict__ ob,
    const float* __restrict__ mb, float* __restrict__ out)
{
    extern __shared__ float sm[];
    float* wgt = sm;                     // [4][9][128]
    int*   gof = (int*)(sm + 4*NPAR);    // [4][9][128]
    float* wsb = sm + 8*NPAR;            // [2][32][128]
    float* vsb = sm + 8*NPAR + 2*WSF;    // [2][32][128]

    const int tid = threadIdx.x;
    const int b   = blockIdx.y;
    const int px0 = blockIdx.x * 128;

    const float* xb = x + b*C_*HW_;

    // ---- stage 0: bilinear params for 9 x 128 samples ----
    for (int t = tid; t < NPAR; t += 256) {
        int k2 = t >> 7, p = t & 127;
        int pg = px0 + p;
        int h  = pg / W_, w = pg % W_;

        float dy = ob[2*k2], dx = ob[2*k2+1], mv = mb[k2];
#pragma unroll
        for (int g = 0; g < CG_; g++) {
            const float* pb = g_part + (((size_t)g*B_ + b)*NJ_)*HW_ + pg;
            dy += pb[(size_t)(2*k2)*HW_];
            dx += pb[(size_t)(2*k2+1)*HW_];
            mv += pb[(size_t)(18+k2)*HW_];
        }
        float m = 2.f / (1.f + __expf(-mv));

        float py = (float)(h - 1 + k2/3) + dy;
        float px = (float)(w - 1 + k2%3) + dx;
        float fy = floorf(py), fx = floorf(px);
        float ly = py - fy,    lx = px - fx;
        int y0 = (int)fy, x0i = (int)fx;
        float vy0 = (y0   >= 0 && y0   < H_) ? 1.f : 0.f;
        float vy1 = (y0+1 >= 0 && y0+1 < H_) ? 1.f : 0.f;
        float vx0 = (x0i   >= 0 && x0i   < W_) ? 1.f : 0.f;
        float vx1 = (x0i+1 >= 0 && x0i+1 < W_) ? 1.f : 0.f;
        int cy0 = min(max(y0, 0), H_-1),   cy1 = min(max(y0+1, 0), H_-1);
        int cx0 = min(max(x0i, 0), W_-1),  cx1 = min(max(x0i+1, 0), W_-1);
        wgt[0*NPAR + t] = (1.f-ly)*(1.f-lx)*vy0*vx0*m;
        wgt[1*NPAR + t] = (1.f-ly)*lx      *vy0*vx1*m;
        wgt[2*NPAR + t] = ly*(1.f-lx)      *vy1*vx0*m;
        wgt[3*NPAR + t] = ly*lx            *vy1*vx1*m;
        gof[0*NPAR + t] = cy0*W_ + cx0;
        gof[1*NPAR + t] = cy0*W_ + cx1;
        gof[2*NPAR + t] = cy1*W_ + cx0;
        gof[3*NPAR + t] = cy1*W_ + cx1;
    }
    __syncthreads();

    const int lane = tid & 31;
    const int wrow = tid >> 5;   // 0..7

    // gather one 32-k chunk into vbuf (chunk-swizzled layout)
    auto do_gather = [&](int kc, float* vbuf) {
#pragma unroll
        for (int it = 0; it < 4; it++) {
            int kk = wrow + it*8;
            int k  = kc + kk;
            int cc = k / 9;
            int k2 = k - cc*9;
            const float* xc = xb + cc*HW_;
#pragma unroll
            for (int rep = 0; rep < 4; rep++) {
                int p = lane + rep*32;
                int t = k2*128 + p;
                float v = wgt[0*NPAR + t]*__ldg(xc + gof[0*NPAR + t])
                        + wgt[1*NPAR + t]*__ldg(xc + gof[1*NPAR + t])
                        + wgt[2*NPAR + t]*__ldg(xc + gof[2*NPAR + t])
                        + wgt[3*NPAR + t]*__ldg(xc + gof[3*NPAR + t]);
                int chunk = p >> 2;
                vbuf[kk*128 + (CSWZ(chunk) << 2) + (p & 3)] = v;
            }
        }
    };

    auto issueW = [&](int buf, int kc) {
        float* wb = wsb + buf*WSF;
        const float* wg = g_Wt + (size_t)kc*O_;
#pragma unroll
        for (int i = 0; i < 4; i++) {
            int idx = tid + i*256;
            int r = idx >> 5, q = idx & 31;
            cp16(wb + r*O_ + CSWZ(q)*4, wg + r*O_ + q*4);
        }
        asm volatile("cp.async.commit_group;");
    };

    const int to = tid & 15;
    const int tp = tid >> 4;
    const int wo0 = CSWZ(to*2)     * 4;
    const int wo1 = CSWZ(to*2 + 1) * 4;
    const int vo0 = CSWZ(tp*2)     * 4;
    const int vo1 = CSWZ(tp*2 + 1) * 4;

    unsigned long long acc2[8][4];
#pragma unroll
    for (int i = 0; i < 8; i++)
#pragma unroll
        for (int j = 0; j < 4; j++) acc2[i][j] = 0ull;

    // prologue: W(0) + gather(0)
    issueW(0, 0);
    do_gather(0, vsb);

    const int NCH = CK_/KCM;   // 18
    for (int c = 0; c < NCH; c++) {
        int cur = c & 1;
        if (c + 1 < NCH) {
            issueW(cur ^ 1, (c+1)*KCM);
            do_gather((c+1)*KCM, vsb + (cur ^ 1)*VSF);
            asm volatile("cp.async.wait_group 1;");
        } else {
            asm volatile("cp.async.wait_group 0;");
        }
        __syncthreads();

        const float* wbuf = wsb + cur*WSF;
        const float* vbuf = vsb + cur*VSF;

#pragma unroll 4
        for (int kk = 0; kk < KCM; kk++) {
            const float* wr = wbuf + kk*128;
            float4 a0 = *(const float4*)(wr + wo0);
            float4 a1 = *(const float4*)(wr + wo1);
            const float* vr = vbuf + kk*128;
            float4 v0 = *(const float4*)(vr + vo0);
            float4 v1 = *(const float4*)(vr + vo1);
            unsigned long long bv0 = ((const unsigned long long*)&v0)[0];
            unsigned long long bv1 = ((const unsigned long long*)&v0)[1];
            unsigned long long bv2 = ((const unsigned long long*)&v1)[0];
            unsigned long long bv3 = ((const unsigned long long*)&v1)[1];
            float av[8] = {a0.x, a0.y, a0.z, a0.w, a1.x, a1.y, a1.z, a1.w};
#pragma unroll
            for (int i = 0; i < 8; i++) {
                unsigned long long ai = pack2(av[i]);
                asm("fma.rn.f32x2 %0, %1, %2, %0;" : "+l"(acc2[i][0]) : "l"(ai), "l"(bv0));
                asm("fma.rn.f32x2 %0, %1, %2, %0;" : "+l"(acc2[i][1]) : "l"(ai), "l"(bv1));
                asm("fma.rn.f32x2 %0, %1, %2, %0;" : "+l"(acc2[i][2]) : "l"(ai), "l"(bv2));
                asm("fma.rn.f32x2 %0, %1, %2, %0;" : "+l"(acc2[i][3]) : "l"(ai), "l"(bv3));
            }
        }
        __syncthreads();
    }

    // epilogue
    const int o0 = to * 8;
    const int p0 = tp * 8;
#pragma unroll
    for (int i = 0; i < 8; i++) {
        float* dst = out + (size_t)(b*O_ + o0 + i)*HW_ + px0 + p0;
        *(float4*)(dst)     = *(float4*)(&acc2[i][0]);
        *(float4*)(dst + 4) = *(float4*)(&acc2[i][2]);
    }
}

// ---------------------------------------------------------------------------
extern "C" void kernel_launch(void* const* d_in, const int* in_sizes, int n_in,
                              void* d_out, int out_size)
{
    const float* x  = (const float*)d_in[0];
    const float* ow = (const float*)d_in[1];
    const float* ob = (const float*)d_in[2];
    const float* mw = (const float*)d_in[3];
    const float* mb = (const float*)d_in[4];
    const float* dw = (const float*)d_in[5];
    float* out = (float*)d_out;

    const int smemF = (8*NPAR + 2*WSF + 2*VSF) * 4;   // 102400 B
    cudaFuncSetAttribute(fused_kernel,
                         cudaFuncAttributeMaxDynamicSharedMemorySize, smemF);

    dim3 gA(3, 3, B_*CG_*2), bA(8, 32);   // 288 blocks
    conv_offmod_partial<<<gA, bA>>>(x, ow, mw);

    transpose_w<<<(O_*CK_ + 255)/256, 256>>>(dw);

    dim3 gF(HW_/128, B_);   // 72 x 4 = 288 blocks
    fused_kernel<<<gF, 256, smemF>>>(x, ob, mb, out);
}

// round 13
// speedup vs baseline: 1.2016x; 1.0758x over previous
#include <cuda_runtime.h>
#include <cstdint>

#define B_  4
#define C_  64
#define H_  96
#define W_  96
#define O_  128
#define HW_ (H_*W_)
#define K2_ 9
#define NJ_ 27
#define CK_ (C_*K2_)   // 576
#define CG_ 4
#define CPG (C_/CG_)   // 16

// scratch
__device__ float g_part[(size_t)CG_*B_*NJ_*HW_];
__device__ float g_Wt[(size_t)CK_*O_];   // transposed deform weights [k][o]

// 4B cp.async with zero-fill predicate (src-size = 0 -> fills 0)
__device__ __forceinline__ void cp4z(float* s, const float* g, unsigned ssz) {
    unsigned sa = (unsigned)__cvta_generic_to_shared(s);
    asm volatile("cp.async.ca.shared.global [%0], [%1], 4, %2;"
                 :: "r"(sa), "l"(g), "r"(ssz));
}
__device__ __forceinline__ void cp16(float* s, const float* g) {
    unsigned sa = (unsigned)__cvta_generic_to_shared(s);
    asm volatile("cp.async.cg.shared.global [%0], [%1], 16;"
                 :: "r"(sa), "l"(g));
}
__device__ __forceinline__ unsigned long long pack2(float v) {
    unsigned long long r;
    unsigned int u = __float_as_uint(v);
    asm("mov.b64 %0, {%1, %1};" : "=l"(r) : "r"(u));
    return r;
}

// ---------------------------------------------------------------------------
// Kernel A: offset+modulator 3x3 conv, partial over 16-channel groups,
// both j-halves in one launch, 4 px/thread.
// NEW: input tiles double-buffered via cp.async (zero-fill halo predicate).
// ---------------------------------------------------------------------------
__global__ void __launch_bounds__(256) conv_offmod_partial(
    const float* __restrict__ x, const float* __restrict__ ow,
    const float* __restrict__ mw)
{
    __shared__ float ws[CPG*14*9];
    __shared__ float xs[2][34*36];

    const int tx = threadIdx.x;
    const int ty = threadIdx.y;
    const int tid = ty*8 + tx;
    const int zz = blockIdx.z;
    const int half = zz & 1;
    const int g = (zz >> 1) & 3;
    const int b = zz >> 3;
    const int JB = half * 14;
    const int jn = half ? 13 : 14;
    const int c0 = g * CPG;
    const int x0t = blockIdx.x*32 - 1;
    const int y0t = blockIdx.y*32 - 1;

    const int jn9 = jn * 9;
    for (int idx = tid; idx < CPG*jn9; idx += 256) {
        int c = idx / jn9, r = idx % jn9;
        int j = r / 9 + JB, t = r % 9;
        float v = (j < 18) ? ow[(j*64 + c0 + c)*9 + t]
                           : mw[((j-18)*64 + c0 + c)*9 + t];
        ws[idx] = v;
    }

    float acc[14][4];
#pragma unroll
    for (int j = 0; j < 14; j++)
#pragma unroll
        for (int i = 0; i < 4; i++) acc[j][i] = 0.f;

    const float* xb = x + (b*C_ + c0)*HW_;

    auto issueX = [&](int buf, int c) {
        const float* xc = xb + c*HW_;
#pragma unroll
        for (int it = 0; it < 5; it++) {
            int idx = tid + it*256;
            if (idx < 34*34) {
                int r = idx / 34, cc = idx % 34;
                int gy = y0t + r, gx = x0t + cc;
                bool ok = (gy >= 0 && gy < H_ && gx >= 0 && gx < W_);
                const float* gp = xc + (ok ? gy*W_ + gx : 0);
                cp4z(&xs[buf][r*36 + cc], gp, ok ? 4u : 0u);
            }
        }
        asm volatile("cp.async.commit_group;");
    };

    issueX(0, 0);

    for (int c = 0; c < CPG; c++) {
        if (c + 1 < CPG) {
            issueX((c+1) & 1, c+1);
            asm volatile("cp.async.wait_group 1;");
        } else {
            asm volatile("cp.async.wait_group 0;");
        }
        __syncthreads();

        const float* xt = xs[c & 1];
        float xv[3][6];
#pragma unroll
        for (int dy = 0; dy < 3; dy++)
#pragma unroll
            for (int dx = 0; dx < 6; dx++)
                xv[dy][dx] = xt[(ty + dy)*36 + tx*4 + dx];

        const float* wc = ws + c*jn9;
#pragma unroll
        for (int j = 0; j < 14; j++) {
            if (j < jn) {
#pragma unroll
                for (int t = 0; t < 9; t++) {
                    float wv = wc[j*9 + t];
#pragma unroll
                    for (int i = 0; i < 4; i++)
                        acc[j][i] = fmaf(wv, xv[t/3][t%3 + i], acc[j][i]);
                }
            }
        }
        __syncthreads();   // protect buffer c&1 before it is re-issued at c+1
    }

    const int h  = y0t + 1 + ty;
    const int w0 = x0t + 1 + tx*4;
    float* outb = g_part + ((size_t)(g*B_ + b)*NJ_ + JB)*HW_ + h*W_ + w0;
#pragma unroll
    for (int j = 0; j < 14; j++) {
        if (j < jn) {
            float4 v = make_float4(acc[j][0], acc[j][1], acc[j][2], acc[j][3]);
            *(float4*)(outb + (size_t)j*HW_) = v;
        }
    }
}

// ---------------------------------------------------------------------------
// Kernel T: transpose deform weights [O][CK] -> [CK][O]
// ---------------------------------------------------------------------------
__global__ void transpose_w(const float* __restrict__ dw)
{
    int i = blockIdx.x*256 + threadIdx.x;
    if (i < O_*CK_) {
        int o = i / CK_, k = i % CK_;
        g_Wt[(size_t)k*O_ + o] = dw[i];
    }
}

// ---------------------------------------------------------------------------
// Kernel F: FUSED gather + GEMM (unchanged from R12).
// ---------------------------------------------------------------------------
#define KCM 32
#define NPAR (K2_*128)
#define WSF (KCM*128)
#define VSF (KCM*128)
#define CSWZ(cx) ((cx) ^ (((cx) >> 3) & 1))

__global__ void __launch_bounds__(256, 2) fused_kernel(
    const float* __restrict__ x, const float* __restrict__ ob,
    const float* __restrict__ mb, float* __restrict__ out)
{
    extern __shared__ float sm[];
    float* wgt = sm;                     // [4][9][128]
    int*   gof = (int*)(sm + 4*NPAR);    // [4][9][128]
    float* wsb = sm + 8*NPAR;            // [2][32][128]
    float* vsb = sm + 8*NPAR + 2*WSF;    // [2][32][128]

    const int tid = threadIdx.x;
    const int b   = blockIdx.y;
    const int px0 = blockIdx.x * 128;

    const float* xb = x + b*C_*HW_;

    for (int t = tid; t < NPAR; t += 256) {
        int k2 = t >> 7, p = t & 127;
        int pg = px0 + p;
        int h  = pg / W_, w = pg % W_;

        float dy = ob[2*k2], dx = ob[2*k2+1], mv = mb[k2];
#pragma unroll
        for (int g = 0; g < CG_; g++) {
            const float* pb = g_part + (((size_t)g*B_ + b)*NJ_)*HW_ + pg;
            dy += pb[(size_t)(2*k2)*HW_];
            dx += pb[(size_t)(2*k2+1)*HW_];
            mv += pb[(size_t)(18+k2)*HW_];
        }
        float m = 2.f / (1.f + __expf(-mv));

        float py = (float)(h - 1 + k2/3) + dy;
        float px = (float)(w - 1 + k2%3) + dx;
        float fy = floorf(py), fx = floorf(px);
        float ly = py - fy,    lx = px - fx;
        int y0 = (int)fy, x0i = (int)fx;
        float vy0 = (y0   >= 0 && y0   < H_) ? 1.f : 0.f;
        float vy1 = (y0+1 >= 0 && y0+1 < H_) ? 1.f : 0.f;
        float vx0 = (x0i   >= 0 && x0i   < W_) ? 1.f : 0.f;
        float vx1 = (x0i+1 >= 0 && x0i+1 < W_) ? 1.f : 0.f;
        int cy0 = min(max(y0, 0), H_-1),   cy1 = min(max(y0+1, 0), H_-1);
        int cx0 = min(max(x0i, 0), W_-1),  cx1 = min(max(x0i+1, 0), W_-1);
        wgt[0*NPAR + t] = (1.f-ly)*(1.f-lx)*vy0*vx0*m;
        wgt[1*NPAR + t] = (1.f-ly)*lx      *vy0*vx1*m;
        wgt[2*NPAR + t] = ly*(1.f-lx)      *vy1*vx0*m;
        wgt[3*NPAR + t] = ly*lx            *vy1*vx1*m;
        gof[0*NPAR + t] = cy0*W_ + cx0;
        gof[1*NPAR + t] = cy0*W_ + cx1;
        gof[2*NPAR + t] = cy1*W_ + cx0;
        gof[3*NPAR + t] = cy1*W_ + cx1;
    }
    __syncthreads();

    const int lane = tid & 31;
    const int wrow = tid >> 5;

    auto do_gather = [&](int kc, float* vbuf) {
#pragma unroll
        for (int it = 0; it < 4; it++) {
            int kk = wrow + it*8;
            int k  = kc + kk;
            int cc = k / 9;
            int k2 = k - cc*9;
            const float* xc = xb + cc*HW_;
#pragma unroll
            for (int rep = 0; rep < 4; rep++) {
                int p = lane + rep*32;
                int t = k2*128 + p;
                float v = wgt[0*NPAR + t]*__ldg(xc + gof[0*NPAR + t])
                        + wgt[1*NPAR + t]*__ldg(xc + gof[1*NPAR + t])
                        + wgt[2*NPAR + t]*__ldg(xc + gof[2*NPAR + t])
                        + wgt[3*NPAR + t]*__ldg(xc + gof[3*NPAR + t]);
                int chunk = p >> 2;
                vbuf[kk*128 + (CSWZ(chunk) << 2) + (p & 3)] = v;
            }
        }
    };

    auto issueW = [&](int buf, int kc) {
        float* wb = wsb + buf*WSF;
        const float* wg = g_Wt + (size_t)kc*O_;
#pragma unroll
        for (int i = 0; i < 4; i++) {
            int idx = tid + i*256;
            int r = idx >> 5, q = idx & 31;
            cp16(wb + r*O_ + CSWZ(q)*4, wg + r*O_ + q*4);
        }
        asm volatile("cp.async.commit_group;");
    };

    const int to = tid & 15;
    const int tp = tid >> 4;
    const int wo0 = CSWZ(to*2)     * 4;
    const int wo1 = CSWZ(to*2 + 1) * 4;
    const int vo0 = CSWZ(tp*2)     * 4;
    const int vo1 = CSWZ(tp*2 + 1) * 4;

    unsigned long long acc2[8][4];
#pragma unroll
    for (int i = 0; i < 8; i++)
#pragma unroll
        for (int j = 0; j < 4; j++) acc2[i][j] = 0ull;

    issueW(0, 0);
    do_gather(0, vsb);

    const int NCH = CK_/KCM;   // 18
    for (int c = 0; c < NCH; c++) {
        int cur = c & 1;
        if (c + 1 < NCH) {
            issueW(cur ^ 1, (c+1)*KCM);
            do_gather((c+1)*KCM, vsb + (cur ^ 1)*VSF);
            asm volatile("cp.async.wait_group 1;");
        } else {
            asm volatile("cp.async.wait_group 0;");
        }
        __syncthreads();

        const float* wbuf = wsb + cur*WSF;
        const float* vbuf = vsb + cur*VSF;

#pragma unroll 4
        for (int kk = 0; kk < KCM; kk++) {
            const float* wr = wbuf + kk*128;
            float4 a0 = *(const float4*)(wr + wo0);
            float4 a1 = *(const float4*)(wr + wo1);
            const float* vr = vbuf + kk*128;
            float4 v0 = *(const float4*)(vr + vo0);
            float4 v1 = *(const float4*)(vr + vo1);
            unsigned long long bv0 = ((const unsigned long long*)&v0)[0];
            unsigned long long bv1 = ((const unsigned long long*)&v0)[1];
            unsigned long long bv2 = ((const unsigned long long*)&v1)[0];
            unsigned long long bv3 = ((const unsigned long long*)&v1)[1];
            float av[8] = {a0.x, a0.y, a0.z, a0.w, a1.x, a1.y, a1.z, a1.w};
#pragma unroll
            for (int i = 0; i < 8; i++) {
                unsigned long long ai = pack2(av[i]);
                asm("fma.rn.f32x2 %0, %1, %2, %0;" : "+l"(acc2[i][0]) : "l"(ai), "l"(bv0));
                asm("fma.rn.f32x2 %0, %1, %2, %0;" : "+l"(acc2[i][1]) : "l"(ai), "l"(bv1));
                asm("fma.rn.f32x2 %0, %1, %2, %0;" : "+l"(acc2[i][2]) : "l"(ai), "l"(bv2));
                asm("fma.rn.f32x2 %0, %1, %2, %0;" : "+l"(acc2[i][3]) : "l"(ai), "l"(bv3));
            }
        }
        __syncthreads();
    }

    const int o0 = to * 8;
    const int p0 = tp * 8;
#pragma unroll
    for (int i = 0; i < 8; i++) {
        float* dst = out + (size_t)(b*O_ + o0 + i)*HW_ + px0 + p0;
        *(float4*)(dst)     = *(float4*)(&acc2[i][0]);
        *(float4*)(dst + 4) = *(float4*)(&acc2[i][2]);
    }
}

// ---------------------------------------------------------------------------
extern "C" void kernel_launch(void* const* d_in, const int* in_sizes, int n_in,
                              void* d_out, int out_size)
{
    const float* x  = (const float*)d_in[0];
    const float* ow = (const float*)d_in[1];
    const float* ob = (const float*)d_in[2];
    const float* mw = (const float*)d_in[3];
    const float* mb = (const float*)d_in[4];
    const float* dw = (const float*)d_in[5];
    float* out = (float*)d_out;

    const int smemF = (8*NPAR + 2*WSF + 2*VSF) * 4;   // 102400 B
    cudaFuncSetAttribute(fused_kernel,
                         cudaFuncAttributeMaxDynamicSharedMemorySize, smemF);

    dim3 gA(3, 3, B_*CG_*2), bA(8, 32);   // 288 blocks
    conv_offmod_partial<<<gA, bA>>>(x, ow, mw);

    transpose_w<<<(O_*CK_ + 255)/256, 256>>>(dw);

    dim3 gF(HW_/128, B_);   // 72 x 4 = 288 blocks
    fused_kernel<<<gF, 256, smemF>>>(x, ob, mb, out);
}

// round 14
// speedup vs baseline: 1.4042x; 1.1686x over previous
#include <cuda_runtime.h>
#include <cstdint>

#define B_  4
#define C_  64
#define H_  96
#define W_  96
#define O_  128
#define HW_ (H_*W_)
#define K2_ 9
#define NJ_ 27
#define CK_ (C_*K2_)   // 576
#define CG_ 4
#define CPG (C_/CG_)   // 16

// scratch
__device__ float g_part[(size_t)CG_*B_*NJ_*HW_];
__device__ float g_Wt[(size_t)CK_*O_];   // transposed weights, k2-major: [(k2*64+c)][o]

// 4B cp.async with zero-fill predicate (src-size = 0 -> fills 0)
__device__ __forceinline__ void cp4z(float* s, const float* g, unsigned ssz) {
    unsigned sa = (unsigned)__cvta_generic_to_shared(s);
    asm volatile("cp.async.ca.shared.global [%0], [%1], 4, %2;"
                 :: "r"(sa), "l"(g), "r"(ssz));
}
__device__ __forceinline__ void cp16(float* s, const float* g) {
    unsigned sa = (unsigned)__cvta_generic_to_shared(s);
    asm volatile("cp.async.cg.shared.global [%0], [%1], 16;"
                 :: "r"(sa), "l"(g));
}
__device__ __forceinline__ unsigned long long pack2(float v) {
    unsigned long long r;
    unsigned int u = __float_as_uint(v);
    asm("mov.b64 %0, {%1, %1};" : "=l"(r) : "r"(u));
    return r;
}

// ---------------------------------------------------------------------------
// Kernel A: offset+modulator 3x3 conv (unchanged from R13)
// ---------------------------------------------------------------------------
__global__ void __launch_bounds__(256) conv_offmod_partial(
    const float* __restrict__ x, const float* __restrict__ ow,
    const float* __restrict__ mw)
{
    __shared__ float ws[CPG*14*9];
    __shared__ float xs[2][34*36];

    const int tx = threadIdx.x;
    const int ty = threadIdx.y;
    const int tid = ty*8 + tx;
    const int zz = blockIdx.z;
    const int half = zz & 1;
    const int g = (zz >> 1) & 3;
    const int b = zz >> 3;
    const int JB = half * 14;
    const int jn = half ? 13 : 14;
    const int c0 = g * CPG;
    const int x0t = blockIdx.x*32 - 1;
    const int y0t = blockIdx.y*32 - 1;

    const int jn9 = jn * 9;
    for (int idx = tid; idx < CPG*jn9; idx += 256) {
        int c = idx / jn9, r = idx % jn9;
        int j = r / 9 + JB, t = r % 9;
        float v = (j < 18) ? ow[(j*64 + c0 + c)*9 + t]
                           : mw[((j-18)*64 + c0 + c)*9 + t];
        ws[idx] = v;
    }

    float acc[14][4];
#pragma unroll
    for (int j = 0; j < 14; j++)
#pragma unroll
        for (int i = 0; i < 4; i++) acc[j][i] = 0.f;

    const float* xb = x + (b*C_ + c0)*HW_;

    auto issueX = [&](int buf, int c) {
        const float* xc = xb + c*HW_;
#pragma unroll
        for (int it = 0; it < 5; it++) {
            int idx = tid + it*256;
            if (idx < 34*34) {
                int r = idx / 34, cc = idx % 34;
                int gy = y0t + r, gx = x0t + cc;
                bool ok = (gy >= 0 && gy < H_ && gx >= 0 && gx < W_);
                const float* gp = xc + (ok ? gy*W_ + gx : 0);
                cp4z(&xs[buf][r*36 + cc], gp, ok ? 4u : 0u);
            }
        }
        asm volatile("cp.async.commit_group;");
    };

    issueX(0, 0);

    for (int c = 0; c < CPG; c++) {
        if (c + 1 < CPG) {
            issueX((c+1) & 1, c+1);
            asm volatile("cp.async.wait_group 1;");
        } else {
            asm volatile("cp.async.wait_group 0;");
        }
        __syncthreads();

        const float* xt = xs[c & 1];
        float xv[3][6];
#pragma unroll
        for (int dy = 0; dy < 3; dy++)
#pragma unroll
            for (int dx = 0; dx < 6; dx++)
                xv[dy][dx] = xt[(ty + dy)*36 + tx*4 + dx];

        const float* wc = ws + c*jn9;
#pragma unroll
        for (int j = 0; j < 14; j++) {
            if (j < jn) {
#pragma unroll
                for (int t = 0; t < 9; t++) {
                    float wv = wc[j*9 + t];
#pragma unroll
                    for (int i = 0; i < 4; i++)
                        acc[j][i] = fmaf(wv, xv[t/3][t%3 + i], acc[j][i]);
                }
            }
        }
        __syncthreads();
    }

    const int h  = y0t + 1 + ty;
    const int w0 = x0t + 1 + tx*4;
    float* outb = g_part + ((size_t)(g*B_ + b)*NJ_ + JB)*HW_ + h*W_ + w0;
#pragma unroll
    for (int j = 0; j < 14; j++) {
        if (j < jn) {
            float4 v = make_float4(acc[j][0], acc[j][1], acc[j][2], acc[j][3]);
            *(float4*)(outb + (size_t)j*HW_) = v;
        }
    }
}

// ---------------------------------------------------------------------------
// Kernel T: transpose deform weights into k2-major order:
// g_Wt[(k2*64 + c)*O + o] = dw[o][c*9 + k2]
// ---------------------------------------------------------------------------
__global__ void transpose_w(const float* __restrict__ dw)
{
    int i = blockIdx.x*256 + threadIdx.x;
    if (i < O_*CK_) {
        int o = i / CK_, r = i % CK_;
        int c = r / 9, k2 = r % 9;
        g_Wt[(size_t)(k2*C_ + c)*O_ + o] = dw[i];
    }
}

// ---------------------------------------------------------------------------
// Kernel F: FUSED gather + GEMM, k2-major K ordering.
// Per chunk (32 k) all k share one k2 -> bilinear params hoisted per rep.
// ---------------------------------------------------------------------------
#define KCM 32
#define NPAR (K2_*128)
#define WSF (KCM*128)
#define VSF (KCM*128)
#define CSWZ(cx) ((cx) ^ (((cx) >> 3) & 1))

__global__ void __launch_bounds__(256, 2) fused_kernel(
    const float* __restrict__ x, const float* __restrict__ ob,
    const float* __restrict__ mb, float* __restrict__ out)
{
    extern __shared__ float sm[];
    float* wgt = sm;                     // [4][9][128]
    int*   gof = (int*)(sm + 4*NPAR);    // [4][9][128]
    float* wsb = sm + 8*NPAR;            // [2][32][128]
    float* vsb = sm + 8*NPAR + 2*WSF;    // [2][32][128]

    const int tid = threadIdx.x;
    const int b   = blockIdx.y;
    const int px0 = blockIdx.x * 128;

    const float* xb = x + b*C_*HW_;

    // ---- stage 0: bilinear params for 9 x 128 samples ----
    for (int t = tid; t < NPAR; t += 256) {
        int k2 = t >> 7, p = t & 127;
        int pg = px0 + p;
        int h  = pg / W_, w = pg % W_;

        float dy = ob[2*k2], dx = ob[2*k2+1], mv = mb[k2];
#pragma unroll
        for (int g = 0; g < CG_; g++) {
            const float* pb = g_part + (((size_t)g*B_ + b)*NJ_)*HW_ + pg;
            dy += pb[(size_t)(2*k2)*HW_];
            dx += pb[(size_t)(2*k2+1)*HW_];
            mv += pb[(size_t)(18+k2)*HW_];
        }
        float m = 2.f / (1.f + __expf(-mv));

        float py = (float)(h - 1 + k2/3) + dy;
        float px = (float)(w - 1 + k2%3) + dx;
        float fy = floorf(py), fx = floorf(px);
        float ly = py - fy,    lx = px - fx;
        int y0 = (int)fy, x0i = (int)fx;
        float vy0 = (y0   >= 0 && y0   < H_) ? 1.f : 0.f;
        float vy1 = (y0+1 >= 0 && y0+1 < H_) ? 1.f : 0.f;
        float vx0 = (x0i   >= 0 && x0i   < W_) ? 1.f : 0.f;
        float vx1 = (x0i+1 >= 0 && x0i+1 < W_) ? 1.f : 0.f;
        int cy0 = min(max(y0, 0), H_-1),   cy1 = min(max(y0+1, 0), H_-1);
        int cx0 = min(max(x0i, 0), W_-1),  cx1 = min(max(x0i+1, 0), W_-1);
        wgt[0*NPAR + t] = (1.f-ly)*(1.f-lx)*vy0*vx0*m;
        wgt[1*NPAR + t] = (1.f-ly)*lx      *vy0*vx1*m;
        wgt[2*NPAR + t] = ly*(1.f-lx)      *vy1*vx0*m;
        wgt[3*NPAR + t] = ly*lx            *vy1*vx1*m;
        gof[0*NPAR + t] = cy0*W_ + cx0;
        gof[1*NPAR + t] = cy0*W_ + cx1;
        gof[2*NPAR + t] = cy1*W_ + cx0;
        gof[3*NPAR + t] = cy1*W_ + cx1;
    }
    __syncthreads();

    const int lane = tid & 31;
    const int wrow = tid >> 5;   // 0..7

    // gather one 32-k chunk: k = kc+kk = k2*64 + c, k2 fixed per chunk
    auto do_gather = [&](int kc, float* vbuf) {
        const int k2    = kc >> 6;      // kc/64
        const int cbase = kc & 63;      // 0 or 32
#pragma unroll
        for (int rep = 0; rep < 4; rep++) {
            int p = lane + rep*32;
            int t = k2*128 + p;
            float w0 = wgt[0*NPAR + t];
            float w1 = wgt[1*NPAR + t];
            float w2 = wgt[2*NPAR + t];
            float w3 = wgt[3*NPAR + t];
            const float* q0 = xb + (size_t)cbase*HW_ + gof[0*NPAR + t];
            const float* q1 = xb + (size_t)cbase*HW_ + gof[1*NPAR + t];
            const float* q2 = xb + (size_t)cbase*HW_ + gof[2*NPAR + t];
            const float* q3 = xb + (size_t)cbase*HW_ + gof[3*NPAR + t];
            int chunk = p >> 2;
            float* vdst = vbuf + (CSWZ(chunk) << 2) + (p & 3);
#pragma unroll
            for (int it = 0; it < 4; it++) {
                int kk = wrow + it*8;
                size_t coff = (size_t)kk*HW_;
                float v = w0*__ldg(q0 + coff) + w1*__ldg(q1 + coff)
                        + w2*__ldg(q2 + coff) + w3*__ldg(q3 + coff);
                vdst[kk*128] = v;
            }
        }
    };

    auto issueW = [&](int buf, int kc) {
        float* wb = wsb + buf*WSF;
        const float* wg = g_Wt + (size_t)kc*O_;
#pragma unroll
        for (int i = 0; i < 4; i++) {
            int idx = tid + i*256;
            int r = idx >> 5, q = idx & 31;
            cp16(wb + r*O_ + CSWZ(q)*4, wg + r*O_ + q*4);
        }
        asm volatile("cp.async.commit_group;");
    };

    const int to = tid & 15;
    const int tp = tid >> 4;
    const int wo0 = CSWZ(to*2)     * 4;
    const int wo1 = CSWZ(to*2 + 1) * 4;
    const int vo0 = CSWZ(tp*2)     * 4;
    const int vo1 = CSWZ(tp*2 + 1) * 4;

    unsigned long long acc2[8][4];
#pragma unroll
    for (int i = 0; i < 8; i++)
#pragma unroll
        for (int j = 0; j < 4; j++) acc2[i][j] = 0ull;

    issueW(0, 0);
    do_gather(0, vsb);

    const int NCH = CK_/KCM;   // 18
    for (int c = 0; c < NCH; c++) {
        int cur = c & 1;
        if (c + 1 < NCH) {
            issueW(cur ^ 1, (c+1)*KCM);
            do_gather((c+1)*KCM, vsb + (cur ^ 1)*VSF);
            asm volatile("cp.async.wait_group 1;");
        } else {
            asm volatile("cp.async.wait_group 0;");
        }
        __syncthreads();

        const float* wbuf = wsb + cur*WSF;
        const float* vbuf = vsb + cur*VSF;

#pragma unroll 4
        for (int kk = 0; kk < KCM; kk++) {
            const float* wr = wbuf + kk*128;
            float4 a0 = *(const float4*)(wr + wo0);
            float4 a1 = *(const float4*)(wr + wo1);
            const float* vr = vbuf + kk*128;
            float4 v0 = *(const float4*)(vr + vo0);
            float4 v1 = *(const float4*)(vr + vo1);
            unsigned long long bv0 = ((const unsigned long long*)&v0)[0];
            unsigned long long bv1 = ((const unsigned long long*)&v0)[1];
            unsigned long long bv2 = ((const unsigned long long*)&v1)[0];
            unsigned long long bv3 = ((const unsigned long long*)&v1)[1];
            float av[8] = {a0.x, a0.y, a0.z, a0.w, a1.x, a1.y, a1.z, a1.w};
#pragma unroll
            for (int i = 0; i < 8; i++) {
                unsigned long long ai = pack2(av[i]);
                asm("fma.rn.f32x2 %0, %1, %2, %0;" : "+l"(acc2[i][0]) : "l"(ai), "l"(bv0));
                asm("fma.rn.f32x2 %0, %1, %2, %0;" : "+l"(acc2[i][1]) : "l"(ai), "l"(bv1));
                asm("fma.rn.f32x2 %0, %1, %2, %0;" : "+l"(acc2[i][2]) : "l"(ai), "l"(bv2));
                asm("fma.rn.f32x2 %0, %1, %2, %0;" : "+l"(acc2[i][3]) : "l"(ai), "l"(bv3));
            }
        }
        __syncthreads();
    }

    const int o0 = to * 8;
    const int p0 = tp * 8;
#pragma unroll
    for (int i = 0; i < 8; i++) {
        float* dst = out + (size_t)(b*O_ + o0 + i)*HW_ + px0 + p0;
        *(float4*)(dst)     = *(float4*)(&acc2[i][0]);
        *(float4*)(dst + 4) = *(float4*)(&acc2[i][2]);
    }
}

// ---------------------------------------------------------------------------
extern "C" void kernel_launch(void* const* d_in, const int* in_sizes, int n_in,
                              void* d_out, int out_size)
{
    const float* x  = (const float*)d_in[0];
    const float* ow = (const float*)d_in[1];
    const float* ob = (const float*)d_in[2];
    const float* mw = (const float*)d_in[3];
    const float* mb = (const float*)d_in[4];
    const float* dw = (const float*)d_in[5];
    float* out = (float*)d_out;

    const int smemF = (8*NPAR + 2*WSF + 2*VSF) * 4;   // 102400 B
    cudaFuncSetAttribute(fused_kernel,
                         cudaFuncAttributeMaxDynamicSharedMemorySize, smemF);

    dim3 gA(3, 3, B_*CG_*2), bA(8, 32);   // 288 blocks
    conv_offmod_partial<<<gA, bA>>>(x, ow, mw);

    transpose_w<<<(O_*CK_ + 255)/256, 256>>>(dw);

    dim3 gF(HW_/128, B_);   // 72 x 4 = 288 blocks
    fused_kernel<<<gF, 256, smemF>>>(x, ob, mb, out);
}